// round 16
// baseline (speedup 1.0000x reference)
#include <cuda_runtime.h>
#include <math.h>

#define DH 64
#define DC 3

typedef unsigned long long ull;

// Lane-interleaved generators with sigma-PERMUTED columns:
// float4 slot ((gen*2+rr)*16+q)*32 + l holds, for row = l+32*rr:
//   ( S[row][2q], S[row][2q+32], S[row][2q+1], S[row][2q+33] )
__device__ float4 g_skew_il[DC * 2 * 16 * 32];
// Lane-interleaved P_sp, same permuted-column mapping.
__device__ float4 g_psp_il[2 * 16 * 32];
// Gram matrix of generators: [S0.S0, S0.S1, S0.S2, S1.S1, S1.S2, S2.S2]
__device__ float g_gram[6];
// P == identity flag
__device__ int g_pident;
// Chebyshev coefficient table: 64 rho-quanta (rho_q = 0.5*qi), 48 floats each.
__device__ float g_ctab[64 * 48];
// Direction-calibrated spectral ratio c(u) = ||A(u)||_2 / ||A(u)||_F,
// 16 alpha-cells x 32 beta-cells over the positive octant.
__device__ float g_cdir[512];

// ONE setup kernel, grid = 82 x 256:
//  blocks 0..15 : interleaved generator + P layouts
//  block 16     : Gram matrix + P-identity check
//  block 17     : Chebyshev coefficient table
//  blocks 18..81: direction calibration (8 warps/block x 64 = 512 dirs)
__global__ void setup_kernel(const float* __restrict__ L,
                             const float* __restrict__ P) {
    int blk = blockIdx.x;
    int tid = threadIdx.x;

    if (blk < 16) {
        int idx = blk * 256 + tid;
        if (idx < DC * 2 * 16 * 32) {
            int l   = idx & 31;
            int q   = (idx >> 5) & 15;
            int rr  = (idx >> 9) & 1;
            int g   = idx >> 10;
            int row = l + 32 * rr;
            const float* Lg = L + g * DH * DH;
            int ca = 2 * q, cb = 2 * q + 32, cc = 2 * q + 1, cd = 2 * q + 33;
            float4 v;
            v.x = 0.5f * (Lg[row * DH + ca] - Lg[ca * DH + row]);
            v.y = 0.5f * (Lg[row * DH + cb] - Lg[cb * DH + row]);
            v.z = 0.5f * (Lg[row * DH + cc] - Lg[cc * DH + row]);
            v.w = 0.5f * (Lg[row * DH + cd] - Lg[cd * DH + row]);
            g_skew_il[idx] = v;
        }
        int pidx = idx - DC * 2 * 16 * 32;
        if (pidx >= 0 && pidx < 2 * 16 * 32) {
            int l   = pidx & 31;
            int q   = (pidx >> 5) & 15;
            int rr  = (pidx >> 9) & 1;
            int row = l + 32 * rr;
            int ca = 2 * q, cb = 2 * q + 32, cc = 2 * q + 1, cd = 2 * q + 33;
            float4 v;
            v.x = P[row * DH + ca];
            v.y = P[row * DH + cb];
            v.z = P[row * DH + cc];
            v.w = P[row * DH + cd];
            g_psp_il[pidx] = v;
        }
        return;
    }

    if (blk == 16) {
        __shared__ float red[8][6];
        __shared__ int nid[8];
        float g[6] = {0.f, 0.f, 0.f, 0.f, 0.f, 0.f};
        int notid = 0;
        for (int j = tid; j < DH * DH; j += 256) {
            int r = j >> 6, c = j & 63;
            float s0 = 0.5f * (L[j] - L[c * DH + r]);
            float s1 = 0.5f * (L[DH * DH + j] - L[DH * DH + c * DH + r]);
            float s2 = 0.5f * (L[2 * DH * DH + j] - L[2 * DH * DH + c * DH + r]);
            g[0] = fmaf(s0, s0, g[0]);
            g[1] = fmaf(s0, s1, g[1]);
            g[2] = fmaf(s0, s2, g[2]);
            g[3] = fmaf(s1, s1, g[3]);
            g[4] = fmaf(s1, s2, g[4]);
            g[5] = fmaf(s2, s2, g[5]);
            float expd = (r == c) ? 1.0f : 0.0f;
            if (P[j] != expd) notid = 1;
        }
        #pragma unroll
        for (int off = 16; off >= 1; off >>= 1) {
            #pragma unroll
            for (int i = 0; i < 6; i++)
                g[i] += __shfl_xor_sync(0xffffffffu, g[i], off);
            notid |= __shfl_xor_sync(0xffffffffu, notid, off);
        }
        if ((tid & 31) == 0) {
            #pragma unroll
            for (int i = 0; i < 6; i++) red[tid >> 5][i] = g[i];
            nid[tid >> 5] = notid;
        }
        __syncthreads();
        if (tid < 6) {
            float s = 0.f;
            #pragma unroll
            for (int w = 0; w < 8; w++) s += red[w][tid];
            g_gram[tid] = s;
        }
        if (tid == 32) {
            int n = 0;
            #pragma unroll
            for (int w = 0; w < 8; w++) n |= nid[w];
            g_pident = !n;
        }
        return;
    }

    if (blk == 17) {
        int t = tid;
        if (t >= 64) return;
        float rho = 0.5f * (float)(t + 1);
        int kmax = (t + 2) / 2 + 9;          // ceil(rho_q)+9
        if (kmax > 47) kmax = 47;
        float J[48];
        int K = kmax + 10;
        float jp = 0.f, jc = 1e-25f;
        float inv_rho = 1.0f / rho;
        for (int kk = K; kk >= 1; kk--) {
            float jm = fmaf(2.0f * (float)kk * inv_rho, jc, -jp);
            if (kk - 1 <= kmax) J[kk - 1] = jm;
            if (fabsf(jm) > 1e24f) {
                jm *= 1e-24f; jc *= 1e-24f;
                for (int z = kk - 1; z <= kmax; z++) J[z] *= 1e-24f;
            }
            jp = jc; jc = jm;
        }
        float s = J[0];
        for (int kk = 2; kk <= kmax; kk += 2) s += 2.0f * J[kk];
        float invs = 1.0f / s;
        for (int kk = 0; kk < 48; kk++)
            g_ctab[t * 48 + kk] =
                (kk > kmax) ? 0.f : ((kk == 0 ? 1.0f : 2.0f) * J[kk] * invs);
        return;
    }

    // blocks 18..81: direction calibration. One warp per direction.
    {
        __shared__ float pv[8][2][DH];
        int w = tid >> 5;
        int l = tid & 31;
        int d = (blk - 18) * 8 + w;          // 0..511
        const float PI_F = 3.14159265358979f;
        float alpha = ((float)(d >> 5) + 0.5f) * (PI_F / 32.0f);  // 16 cells / (pi/2)
        float beta  = ((float)(d & 31) + 0.5f) * (PI_F / 64.0f);  // 32 cells / (pi/2)
        float u0 = cosf(alpha) * cosf(beta);
        float u1 = cosf(alpha) * sinf(beta);
        float u2 = sinf(alpha);

        // Build rows l, l+32 of A(u); accumulate F^2. (Uncoalesced: setup-only.)
        float Ar0[DH], Ar1[DH];
        float fs = 0.f;
        for (int c = 0; c < DH; c++) {
            int row = l;
            float a0 = 0.5f * (u0 * (L[row * DH + c] - L[c * DH + row])
                             + u1 * (L[DH*DH + row * DH + c] - L[DH*DH + c * DH + row])
                             + u2 * (L[2*DH*DH + row * DH + c] - L[2*DH*DH + c * DH + row]));
            row = l + 32;
            float a1 = 0.5f * (u0 * (L[row * DH + c] - L[c * DH + row])
                             + u1 * (L[DH*DH + row * DH + c] - L[DH*DH + c * DH + row])
                             + u2 * (L[2*DH*DH + row * DH + c] - L[2*DH*DH + c * DH + row]));
            Ar0[c] = a0; Ar1[c] = a1;
            fs += a0 * a0 + a1 * a1;
        }
        #pragma unroll
        for (int off = 16; off >= 1; off >>= 1)
            fs += __shfl_xor_sync(0xffffffffu, fs, off);
        float F = sqrtf(fmaxf(fs, 1e-30f));
        float scl = 4.0f / F;                 // iterate with 4*A/F (ratio ~ O(1))
        for (int c = 0; c < DH; c++) { Ar0[c] *= scl; Ar1[c] *= scl; }

        // init v: lane-dependent pseudo-random
        pv[w][0][l]      = (float)((l * 1103515245u + 12345u) & 0xffffu) * (1.f/65536.f) - 0.5f;
        pv[w][0][l + 32] = (float)(((l + 32) * 1103515245u + 12345u) & 0xffffu) * (1.f/65536.f) - 0.5f;
        __syncwarp();

        float sprev = 1.f, scur = 1.f;
        int cur = 0;
        for (int it = 1; it <= 30; it++) {
            float o0 = 0.f, o1 = 0.f;
            for (int c = 0; c < DH; c++) {
                float vc = pv[w][cur][c];
                o0 = fmaf(Ar0[c], vc, o0);
                o1 = fmaf(Ar1[c], vc, o1);
            }
            pv[w][cur ^ 1][l]      = o0;
            pv[w][cur ^ 1][l + 32] = o1;
            __syncwarp();
            cur ^= 1;
            if (it >= 29) {
                float s = o0 * o0 + o1 * o1;
                #pragma unroll
                for (int off = 16; off >= 1; off >>= 1)
                    s += __shfl_xor_sync(0xffffffffu, s, off);
                if (it == 29) sprev = s; else scur = s;
            }
        }
        // c = (||v30||/||v29||)/4 = mu1/F estimate (from below)
        float cdir = 0.25f * sqrtf(scur / fmaxf(sprev, 1e-30f));
        if (l == 0) g_cdir[d] = cdir;
        return;
    }
}

// ---- packed f32x2 helpers ----
__device__ __forceinline__ ull pack2(float lo, float hi) {
    float2 t = make_float2(lo, hi);
    return *reinterpret_cast<ull*>(&t);
}
__device__ __forceinline__ float2 unpack2(ull v) {
    return *reinterpret_cast<float2*>(&v);
}
__device__ __forceinline__ void ffma2(ull& d, ull a, ull b) {
    asm("fma.rn.f32x2 %0, %1, %2, %0;" : "+l"(d) : "l"(a), "l"(b));
}
__device__ __forceinline__ ull add2(ull a, ull b) {
    ull r; asm("add.rn.f32x2 %0, %1, %2;" : "=l"(r) : "l"(a), "l"(b));
    return r;
}

// Full-row matvec over the permuted vector: lane owns rows l, l+32.
__device__ __forceinline__ void matvec_fr(const ull* A0, const ull* A1,
                                          const float* v,
                                          float& o0, float& o1)
{
    const ulonglong2* vv = reinterpret_cast<const ulonglong2*>(v);
    ull a0[4] = {0ull, 0ull, 0ull, 0ull};
    ull a1[4] = {0ull, 0ull, 0ull, 0ull};
    #pragma unroll
    for (int q = 0; q < 16; q++) {
        ulonglong2 t = vv[q];
        ffma2(a0[(2 * q)     & 3], A0[2 * q],     t.x);
        ffma2(a0[(2 * q + 1) & 3], A0[2 * q + 1], t.y);
        ffma2(a1[(2 * q)     & 3], A1[2 * q],     t.x);
        ffma2(a1[(2 * q + 1) & 3], A1[2 * q + 1], t.y);
    }
    float2 f0 = unpack2(add2(add2(a0[0], a0[1]), add2(a0[2], a0[3])));
    o0 = f0.x + f0.y;
    float2 f1 = unpack2(add2(add2(a1[0], a1[1]), add2(a1[2], a1[3])));
    o1 = f1.x + f1.y;
}

// One Chebyshev term; pa = phi_{k-2} in, phi_k out (in-place rotation).
template <int B1, int BF>
__device__ __forceinline__ void cheb_iter(
    float (*sv)[DH], const ull* A0, const ull* A1, const float* scoef,
    float& y0, float& y1, float& pa0, float& pa1, int kk, int l)
{
    float o0, o1;
    matvec_fr(A0, A1, sv[B1], o0, o1);
    float cf = scoef[kk];
    float pn0 = o0 + pa0;
    float pn1 = o1 + pa1;
    y0 = fmaf(cf, pn0, y0);
    y1 = fmaf(cf, pn1, y1);
    pa0 = pn0;
    pa1 = pn1;
    *reinterpret_cast<float2*>(&sv[BF][2 * l]) = make_float2(pn0, pn1);
    __syncwarp();
}

__global__ __launch_bounds__(32, 12)
void liepe_expmv_kernel(const float* __restrict__ x,
                        const float* __restrict__ rg,
                        float* __restrict__ out)
{
    __shared__ __align__(16) float sv[2][DH];
    __shared__ float scoef[64];

    const int l = threadIdx.x;
    const int pos = blockIdx.x;

    const float r0 = __ldg(&rg[pos * DC + 0]);
    const float r1 = __ldg(&rg[pos * DC + 1]);
    const float r2 = __ldg(&rg[pos * DC + 2]);

    // ---- rho: direction-calibrated spectral estimate ----
    int qi;
    {
        float g0 = __ldg(&g_gram[0]), g1 = __ldg(&g_gram[1]);
        float g2 = __ldg(&g_gram[2]), g3 = __ldg(&g_gram[3]);
        float g4 = __ldg(&g_gram[4]), g5 = __ldg(&g_gram[5]);
        float F2 = r0 * r0 * g0 + r1 * r1 * g3 + r2 * r2 * g5
                 + 2.0f * (r0 * r1 * g1 + r0 * r2 * g2 + r1 * r2 * g4);
        float Fn = sqrtf(fmaxf(F2, 1e-30f));

        const float PI_F = 3.14159265358979f;
        float alpha = atan2f(r2, sqrtf(r0 * r0 + r1 * r1));
        float beta  = atan2f(r1, r0);
        int di = (int)(alpha * (32.0f / PI_F));
        int dj = (int)(beta  * (64.0f / PI_F));
        if (di < 0) di = 0; if (di > 15) di = 15;
        if (dj < 0) dj = 0; if (dj > 31) dj = 31;
        float c = __ldg(&g_cdir[di * 32 + dj]);
        // 1.12 margin (PI underestimate + grid half-cell + fluctuation);
        // clamp by rigorous ||A||_2 <= ||A||_F.
        float rho = fminf(1.12f * c, 1.0f) * Fn;
        qi = (int)ceilf(rho * 2.0f);
        if (qi < 1)  qi = 1;
        if (qi > 64) qi = 64;
    }
    const float rho_q = 0.5f * (float)qi;
    int kmax = (qi + 1) / 2 + 9;           // ceil(rho_q)+9
    if (kmax > 47) kmax = 47;

    // ---- coefficients from precomputed table ----
    {
        const float* row = g_ctab + (qi - 1) * 48;
        scoef[l] = __ldg(&row[l]);
        scoef[l + 32] = (l < 16) ? __ldg(&row[l + 32]) : 0.f;
    }

    // ---- e = P_sp @ x (fast path: P == I) ----
    float e0, e1;
    if (g_pident) {
        e0 = x[pos * DH + l];
        e1 = x[pos * DH + l + 32];
    } else {
        *reinterpret_cast<float2*>(&sv[0][2 * l]) =
            make_float2(x[pos * DH + l], x[pos * DH + l + 32]);
        __syncwarp();
        const float4* vq4 = reinterpret_cast<const float4*>(sv[0]);
        float d0 = 0.f, d1 = 0.f;
        #pragma unroll
        for (int q = 0; q < 16; q++) {
            float4 vq = vq4[q];
            float4 p0 = __ldg(&g_psp_il[(0 * 16 + q) * 32 + l]);
            float4 p1 = __ldg(&g_psp_il[(1 * 16 + q) * 32 + l]);
            d0 = fmaf(p0.x, vq.x, fmaf(p0.y, vq.y,
                 fmaf(p0.z, vq.z, fmaf(p0.w, vq.w, d0))));
            d1 = fmaf(p1.x, vq.x, fmaf(p1.y, vq.y,
                 fmaf(p1.z, vq.z, fmaf(p1.w, vq.w, d1))));
        }
        e0 = d0; e1 = d1;
        __syncwarp();
    }
    *reinterpret_cast<float2*>(&sv[0][2 * l]) = make_float2(e0, e1);
    __syncwarp();

    // ---- build C = (2/rho_q)*A rows l and l+32 (permuted cols) ----
    ull A0[32], A1[32];
    {
        const float cs = 2.0f / rho_q;
        const float c0 = r0 * cs, c1f = r1 * cs, c2f = r2 * cs;
        #pragma unroll
        for (int rr = 0; rr < 2; rr++) {
            ull* Ad = rr ? A1 : A0;
            #pragma unroll
            for (int q = 0; q < 16; q++) {
                int base = (rr * 16 + q) * 32 + l;
                float4 v0 = __ldg(&g_skew_il[base]);
                float4 v1 = __ldg(&g_skew_il[1024 + base]);
                float4 v2 = __ldg(&g_skew_il[2048 + base]);
                float ax = fmaf(c2f, v2.x, fmaf(c1f, v1.x, c0 * v0.x));
                float ay = fmaf(c2f, v2.y, fmaf(c1f, v1.y, c0 * v0.y));
                float az = fmaf(c2f, v2.z, fmaf(c1f, v1.z, c0 * v0.z));
                float aw = fmaf(c2f, v2.w, fmaf(c1f, v1.w, c0 * v0.w));
                Ad[2 * q]     = pack2(ax, ay);
                Ad[2 * q + 1] = pack2(az, aw);
            }
        }
    }

    // ---- y = coef0*phi0; phi1 = 0.5*C*phi0 -> sv[1] ----
    float cf0 = scoef[0];
    float y0 = cf0 * e0, y1 = cf0 * e1;
    float pa0 = e0, pa1 = e1;
    float pb0, pb1;
    {
        float o0, o1;
        matvec_fr(A0, A1, sv[0], o0, o1);
        float cf1 = scoef[1];
        pb0 = 0.5f * o0;
        pb1 = 0.5f * o1;
        y0 = fmaf(cf1, pb0, y0);
        y1 = fmaf(cf1, pb1, y1);
        *reinterpret_cast<float2*>(&sv[1][2 * l]) = make_float2(pb0, pb1);
        __syncwarp();
    }

    // ---- Chebyshev loop: alternate smem buffers AND register pairs ----
    {
        int kk = 2;
        while (kk <= kmax) {
            cheb_iter<1, 0>(sv, A0, A1, scoef, y0, y1, pa0, pa1, kk, l);
            if (++kk > kmax) break;
            cheb_iter<0, 1>(sv, A0, A1, scoef, y0, y1, pb0, pb1, kk, l);
            ++kk;
        }
    }

    out[pos * DH + l]      = y0;
    out[pos * DH + l + 32] = y1;
}

extern "C" void kernel_launch(void* const* d_in, const int* in_sizes, int n_in,
                              void* d_out, int out_size)
{
    const float* x = (const float*)d_in[0];   // [B,S,64]
    const float* r = (const float*)d_in[1];   // [B,S,3]
    const float* L = (const float*)d_in[2];   // [3,64,64]
    const float* P = (const float*)d_in[3];   // [64,64]
    float* out = (float*)d_out;

    int npos = in_sizes[0] / DH;              // B*S

    setup_kernel<<<82, 256>>>(L, P);
    liepe_expmv_kernel<<<npos, 32>>>(x, r, out);
}

// round 17
// speedup vs baseline: 1.1123x; 1.1123x over previous
#include <cuda_runtime.h>
#include <math.h>

#define DH 64
#define DC 3

typedef unsigned long long ull;

// Lane-interleaved generators with sigma-PERMUTED columns:
// float4 slot ((gen*2+rr)*16+q)*32 + l holds, for row = l+32*rr:
//   ( S[row][2q], S[row][2q+32], S[row][2q+1], S[row][2q+33] )
__device__ float4 g_skew_il[DC * 2 * 16 * 32];
// Lane-interleaved P_sp, same permuted-column mapping.
__device__ float4 g_psp_il[2 * 16 * 32];
// Gram matrix of generators: [S0.S0, S0.S1, S0.S2, S1.S1, S1.S2, S2.S2]
__device__ float g_gram[6];
// P == identity flag
__device__ int g_pident;
// Chebyshev coefficient table: 64 rho-quanta (rho_q = 0.5*qi), 48 floats each.
__device__ float g_ctab[64 * 48];
// Direction-calibrated spectral ratio c(u) = ||A(u)||_2 / ||A(u)||_F,
// 8 alpha-cells x 16 beta-cells over the positive octant.
__device__ float g_cdir[128];

// ---- packed f32x2 helpers ----
__device__ __forceinline__ ull pack2(float lo, float hi) {
    float2 t = make_float2(lo, hi);
    return *reinterpret_cast<ull*>(&t);
}
__device__ __forceinline__ float2 unpack2(ull v) {
    return *reinterpret_cast<float2*>(&v);
}
__device__ __forceinline__ void ffma2(ull& d, ull a, ull b) {
    asm("fma.rn.f32x2 %0, %1, %2, %0;" : "+l"(d) : "l"(a), "l"(b));
}
__device__ __forceinline__ ull add2(ull a, ull b) {
    ull r; asm("add.rn.f32x2 %0, %1, %2;" : "=l"(r) : "l"(a), "l"(b));
    return r;
}
__device__ __forceinline__ float warp_sum32(float v) {
    #pragma unroll
    for (int off = 16; off >= 1; off >>= 1)
        v += __shfl_xor_sync(0xffffffffu, v, off);
    return v;
}

// Build packed rows l and l+32 of c0*S0+c1*S1+c2*S2 from the interleaved
// layout (coalesced). Shared by main + calibration kernels.
__device__ __forceinline__ void build_rows(ull* A0, ull* A1, int l,
                                           float c0, float c1f, float c2f)
{
    #pragma unroll
    for (int rr = 0; rr < 2; rr++) {
        ull* Ad = rr ? A1 : A0;
        #pragma unroll
        for (int q = 0; q < 16; q++) {
            int base = (rr * 16 + q) * 32 + l;
            float4 v0 = __ldg(&g_skew_il[base]);
            float4 v1 = __ldg(&g_skew_il[1024 + base]);
            float4 v2 = __ldg(&g_skew_il[2048 + base]);
            float ax = fmaf(c2f, v2.x, fmaf(c1f, v1.x, c0 * v0.x));
            float ay = fmaf(c2f, v2.y, fmaf(c1f, v1.y, c0 * v0.y));
            float az = fmaf(c2f, v2.z, fmaf(c1f, v1.z, c0 * v0.z));
            float aw = fmaf(c2f, v2.w, fmaf(c1f, v1.w, c0 * v0.w));
            Ad[2 * q]     = pack2(ax, ay);
            Ad[2 * q + 1] = pack2(az, aw);
        }
    }
}

// Full-row matvec over the permuted vector: lane owns rows l, l+32.
__device__ __forceinline__ void matvec_fr(const ull* A0, const ull* A1,
                                          const float* v,
                                          float& o0, float& o1)
{
    const ulonglong2* vv = reinterpret_cast<const ulonglong2*>(v);
    ull a0[4] = {0ull, 0ull, 0ull, 0ull};
    ull a1[4] = {0ull, 0ull, 0ull, 0ull};
    #pragma unroll
    for (int q = 0; q < 16; q++) {
        ulonglong2 t = vv[q];
        ffma2(a0[(2 * q)     & 3], A0[2 * q],     t.x);
        ffma2(a0[(2 * q + 1) & 3], A0[2 * q + 1], t.y);
        ffma2(a1[(2 * q)     & 3], A1[2 * q],     t.x);
        ffma2(a1[(2 * q + 1) & 3], A1[2 * q + 1], t.y);
    }
    float2 f0 = unpack2(add2(add2(a0[0], a0[1]), add2(a0[2], a0[3])));
    o0 = f0.x + f0.y;
    float2 f1 = unpack2(add2(add2(a1[0], a1[1]), add2(a1[2], a1[3])));
    o1 = f1.x + f1.y;
}

// ONE setup kernel, grid = 18 x 256 (layouts, Gram+identity, coef table).
__global__ void setup_kernel(const float* __restrict__ L,
                             const float* __restrict__ P) {
    int blk = blockIdx.x;
    int tid = threadIdx.x;

    if (blk < 16) {
        int idx = blk * 256 + tid;
        if (idx < DC * 2 * 16 * 32) {
            int l   = idx & 31;
            int q   = (idx >> 5) & 15;
            int rr  = (idx >> 9) & 1;
            int g   = idx >> 10;
            int row = l + 32 * rr;
            const float* Lg = L + g * DH * DH;
            int ca = 2 * q, cb = 2 * q + 32, cc = 2 * q + 1, cd = 2 * q + 33;
            float4 v;
            v.x = 0.5f * (Lg[row * DH + ca] - Lg[ca * DH + row]);
            v.y = 0.5f * (Lg[row * DH + cb] - Lg[cb * DH + row]);
            v.z = 0.5f * (Lg[row * DH + cc] - Lg[cc * DH + row]);
            v.w = 0.5f * (Lg[row * DH + cd] - Lg[cd * DH + row]);
            g_skew_il[idx] = v;
        }
        int pidx = idx - DC * 2 * 16 * 32;
        if (pidx >= 0 && pidx < 2 * 16 * 32) {
            int l   = pidx & 31;
            int q   = (pidx >> 5) & 15;
            int rr  = (pidx >> 9) & 1;
            int row = l + 32 * rr;
            int ca = 2 * q, cb = 2 * q + 32, cc = 2 * q + 1, cd = 2 * q + 33;
            float4 v;
            v.x = P[row * DH + ca];
            v.y = P[row * DH + cb];
            v.z = P[row * DH + cc];
            v.w = P[row * DH + cd];
            g_psp_il[pidx] = v;
        }
        return;
    }

    if (blk == 16) {
        __shared__ float red[8][6];
        __shared__ int nid[8];
        float g[6] = {0.f, 0.f, 0.f, 0.f, 0.f, 0.f};
        int notid = 0;
        for (int j = tid; j < DH * DH; j += 256) {
            int r = j >> 6, c = j & 63;
            float s0 = 0.5f * (L[j] - L[c * DH + r]);
            float s1 = 0.5f * (L[DH * DH + j] - L[DH * DH + c * DH + r]);
            float s2 = 0.5f * (L[2 * DH * DH + j] - L[2 * DH * DH + c * DH + r]);
            g[0] = fmaf(s0, s0, g[0]);
            g[1] = fmaf(s0, s1, g[1]);
            g[2] = fmaf(s0, s2, g[2]);
            g[3] = fmaf(s1, s1, g[3]);
            g[4] = fmaf(s1, s2, g[4]);
            g[5] = fmaf(s2, s2, g[5]);
            float expd = (r == c) ? 1.0f : 0.0f;
            if (P[j] != expd) notid = 1;
        }
        #pragma unroll
        for (int off = 16; off >= 1; off >>= 1) {
            #pragma unroll
            for (int i = 0; i < 6; i++)
                g[i] += __shfl_xor_sync(0xffffffffu, g[i], off);
            notid |= __shfl_xor_sync(0xffffffffu, notid, off);
        }
        if ((tid & 31) == 0) {
            #pragma unroll
            for (int i = 0; i < 6; i++) red[tid >> 5][i] = g[i];
            nid[tid >> 5] = notid;
        }
        __syncthreads();
        if (tid < 6) {
            float s = 0.f;
            #pragma unroll
            for (int w = 0; w < 8; w++) s += red[w][tid];
            g_gram[tid] = s;
        }
        if (tid == 32) {
            int n = 0;
            #pragma unroll
            for (int w = 0; w < 8; w++) n |= nid[w];
            g_pident = !n;
        }
        return;
    }

    // blk == 17: coefficient table; thread t: qi = t+1, rho_q = 0.5*(t+1)
    {
        int t = tid;
        if (t >= 64) return;
        float rho = 0.5f * (float)(t + 1);
        int kmax = (t + 2) / 2 + 8;          // ceil(rho_q)+8
        if (kmax > 47) kmax = 47;
        float J[48];
        int K = kmax + 10;
        float jp = 0.f, jc = 1e-25f;
        float inv_rho = 1.0f / rho;
        for (int kk = K; kk >= 1; kk--) {
            float jm = fmaf(2.0f * (float)kk * inv_rho, jc, -jp);
            if (kk - 1 <= kmax) J[kk - 1] = jm;
            if (fabsf(jm) > 1e24f) {
                jm *= 1e-24f; jc *= 1e-24f;
                for (int z = kk - 1; z <= kmax; z++) J[z] *= 1e-24f;
            }
            jp = jc; jc = jm;
        }
        float s = J[0];
        for (int kk = 2; kk <= kmax; kk += 2) s += 2.0f * J[kk];
        float invs = 1.0f / s;
        for (int kk = 0; kk < 48; kk++)
            g_ctab[t * 48 + kk] =
                (kk > kmax) ? 0.f : ((kk == 0 ? 1.0f : 2.0f) * J[kk] * invs);
    }
}

// Calibration kernel (separate launch AFTER setup): one 32-thread block per
// direction, using the interleaved layout + register matvec (coalesced, fast).
// Permutation of rows/cols leaves all norms invariant.
__global__ __launch_bounds__(32, 12)
void calib_kernel() {
    __shared__ __align__(16) float sv[2][DH];
    const int l = threadIdx.x;
    const int d = blockIdx.x;            // 0..127 = 8 alpha x 16 beta
    const float PI_F = 3.14159265358979f;
    float alpha = ((float)(d >> 4) + 0.5f) * (PI_F / 16.0f);
    float beta  = ((float)(d & 15) + 0.5f) * (PI_F / 32.0f);
    float u0 = cosf(alpha) * cosf(beta);
    float u1 = cosf(alpha) * sinf(beta);
    float u2 = sinf(alpha);

    // F(u) from Gram
    float F;
    {
        float g0 = g_gram[0], g1 = g_gram[1], g2 = g_gram[2];
        float g3 = g_gram[3], g4 = g_gram[4], g5 = g_gram[5];
        float F2 = u0 * u0 * g0 + u1 * u1 * g3 + u2 * u2 * g5
                 + 2.0f * (u0 * u1 * g1 + u0 * u2 * g2 + u1 * u2 * g4);
        F = sqrtf(fmaxf(F2, 1e-30f));
    }

    // Build rows of 4*A(u)/F  (spectral norm ~ 4c ~ 1: stable iteration)
    ull A0[32], A1[32];
    {
        float cs = 4.0f / F;
        build_rows(A0, A1, l, u0 * cs, u1 * cs, u2 * cs);
    }

    // init v (fixed pseudo-random), permuted storage
    {
        float v0 = (float)((l * 1103515245u + 12345u) & 0xffffu) * (1.f/65536.f) - 0.5f;
        float v1 = (float)(((l + 32) * 747796405u + 12345u) & 0xffffu) * (1.f/65536.f) - 0.5f;
        *reinterpret_cast<float2*>(&sv[0][2 * l]) = make_float2(v0, v1);
    }
    __syncwarp();

    float sprev = 1.f, scur = 1.f;
    int cur = 0;
    for (int it = 1; it <= 18; it++) {
        float o0, o1;
        matvec_fr(A0, A1, sv[cur], o0, o1);
        *reinterpret_cast<float2*>(&sv[cur ^ 1][2 * l]) = make_float2(o0, o1);
        __syncwarp();
        cur ^= 1;
        if (it == 17) sprev = warp_sum32(o0 * o0 + o1 * o1);
        if (it == 18) scur  = warp_sum32(o0 * o0 + o1 * o1);
    }
    // c = mu1/F estimate = (||v18||/||v17||)/4
    float cdir = 0.25f * sqrtf(scur / fmaxf(sprev, 1e-30f));
    if (l == 0) g_cdir[d] = cdir;
}

// One Chebyshev term; pa = phi_{k-2} in, phi_k out (in-place rotation).
template <int B1, int BF>
__device__ __forceinline__ void cheb_iter(
    float (*sv)[DH], const ull* A0, const ull* A1, const float* scoef,
    float& y0, float& y1, float& pa0, float& pa1, int kk, int l)
{
    float o0, o1;
    matvec_fr(A0, A1, sv[B1], o0, o1);
    float cf = scoef[kk];
    float pn0 = o0 + pa0;
    float pn1 = o1 + pa1;
    y0 = fmaf(cf, pn0, y0);
    y1 = fmaf(cf, pn1, y1);
    pa0 = pn0;
    pa1 = pn1;
    *reinterpret_cast<float2*>(&sv[BF][2 * l]) = make_float2(pn0, pn1);
    __syncwarp();
}

__global__ __launch_bounds__(32, 12)
void liepe_expmv_kernel(const float* __restrict__ x,
                        const float* __restrict__ rg,
                        float* __restrict__ out)
{
    __shared__ __align__(16) float sv[2][DH];
    __shared__ float scoef[64];

    const int l = threadIdx.x;
    const int pos = blockIdx.x;

    const float r0 = __ldg(&rg[pos * DC + 0]);
    const float r1 = __ldg(&rg[pos * DC + 1]);
    const float r2 = __ldg(&rg[pos * DC + 2]);

    // ---- rho: direction-calibrated spectral estimate ----
    int qi;
    {
        float g0 = __ldg(&g_gram[0]), g1 = __ldg(&g_gram[1]);
        float g2 = __ldg(&g_gram[2]), g3 = __ldg(&g_gram[3]);
        float g4 = __ldg(&g_gram[4]), g5 = __ldg(&g_gram[5]);
        float F2 = r0 * r0 * g0 + r1 * r1 * g3 + r2 * r2 * g5
                 + 2.0f * (r0 * r1 * g1 + r0 * r2 * g2 + r1 * r2 * g4);
        float Fn = sqrtf(fmaxf(F2, 1e-30f));

        const float PI_F = 3.14159265358979f;
        float alpha = atan2f(r2, sqrtf(r0 * r0 + r1 * r1));
        float beta  = atan2f(r1, r0);
        int di = (int)(alpha * (16.0f / PI_F));
        int dj = (int)(beta  * (32.0f / PI_F));
        if (di < 0) di = 0; if (di > 7)  di = 7;
        if (dj < 0) dj = 0; if (dj > 15) dj = 15;
        float c = __ldg(&g_cdir[di * 16 + dj]);
        // 1.14 margin (18-step PI underestimate + grid cell + fluctuation);
        // clamp by rigorous ||A||_2 <= ||A||_F.
        float rho = fminf(1.14f * c, 1.0f) * Fn;
        qi = (int)ceilf(rho * 2.0f);
        if (qi < 1)  qi = 1;
        if (qi > 64) qi = 64;
    }
    const float rho_q = 0.5f * (float)qi;
    int kmax = (qi + 1) / 2 + 8;           // ceil(rho_q)+8
    if (kmax > 47) kmax = 47;

    // ---- coefficients from precomputed table ----
    {
        const float* row = g_ctab + (qi - 1) * 48;
        scoef[l] = __ldg(&row[l]);
        scoef[l + 32] = (l < 16) ? __ldg(&row[l + 32]) : 0.f;
    }

    // ---- e = P_sp @ x (fast path: P == I) ----
    float e0, e1;
    if (g_pident) {
        e0 = x[pos * DH + l];
        e1 = x[pos * DH + l + 32];
    } else {
        *reinterpret_cast<float2*>(&sv[0][2 * l]) =
            make_float2(x[pos * DH + l], x[pos * DH + l + 32]);
        __syncwarp();
        const float4* vq4 = reinterpret_cast<const float4*>(sv[0]);
        float d0 = 0.f, d1 = 0.f;
        #pragma unroll
        for (int q = 0; q < 16; q++) {
            float4 vq = vq4[q];
            float4 p0 = __ldg(&g_psp_il[(0 * 16 + q) * 32 + l]);
            float4 p1 = __ldg(&g_psp_il[(1 * 16 + q) * 32 + l]);
            d0 = fmaf(p0.x, vq.x, fmaf(p0.y, vq.y,
                 fmaf(p0.z, vq.z, fmaf(p0.w, vq.w, d0))));
            d1 = fmaf(p1.x, vq.x, fmaf(p1.y, vq.y,
                 fmaf(p1.z, vq.z, fmaf(p1.w, vq.w, d1))));
        }
        e0 = d0; e1 = d1;
        __syncwarp();
    }
    *reinterpret_cast<float2*>(&sv[0][2 * l]) = make_float2(e0, e1);
    __syncwarp();

    // ---- build C = (2/rho_q)*A rows l and l+32 (permuted cols) ----
    ull A0[32], A1[32];
    {
        const float cs = 2.0f / rho_q;
        build_rows(A0, A1, l, r0 * cs, r1 * cs, r2 * cs);
    }

    // ---- y = coef0*phi0; phi1 = 0.5*C*phi0 -> sv[1] ----
    float cf0 = scoef[0];
    float y0 = cf0 * e0, y1 = cf0 * e1;
    float pa0 = e0, pa1 = e1;
    float pb0, pb1;
    {
        float o0, o1;
        matvec_fr(A0, A1, sv[0], o0, o1);
        float cf1 = scoef[1];
        pb0 = 0.5f * o0;
        pb1 = 0.5f * o1;
        y0 = fmaf(cf1, pb0, y0);
        y1 = fmaf(cf1, pb1, y1);
        *reinterpret_cast<float2*>(&sv[1][2 * l]) = make_float2(pb0, pb1);
        __syncwarp();
    }

    // ---- Chebyshev loop: alternate smem buffers AND register pairs ----
    {
        int kk = 2;
        while (kk <= kmax) {
            cheb_iter<1, 0>(sv, A0, A1, scoef, y0, y1, pa0, pa1, kk, l);
            if (++kk > kmax) break;
            cheb_iter<0, 1>(sv, A0, A1, scoef, y0, y1, pb0, pb1, kk, l);
            ++kk;
        }
    }

    out[pos * DH + l]      = y0;
    out[pos * DH + l + 32] = y1;
}

extern "C" void kernel_launch(void* const* d_in, const int* in_sizes, int n_in,
                              void* d_out, int out_size)
{
    const float* x = (const float*)d_in[0];   // [B,S,64]
    const float* r = (const float*)d_in[1];   // [B,S,3]
    const float* L = (const float*)d_in[2];   // [3,64,64]
    const float* P = (const float*)d_in[3];   // [64,64]
    float* out = (float*)d_out;

    int npos = in_sizes[0] / DH;              // B*S

    setup_kernel<<<18, 256>>>(L, P);
    calib_kernel<<<128, 32>>>();
    liepe_expmv_kernel<<<npos, 32>>>(x, r, out);
}